// round 1
// baseline (speedup 1.0000x reference)
#include <cuda_runtime.h>

// Problem constants (fixed by the dataset)
#define NQ       50000
#define MNB      32          // neighbors per query
#define NKP      15          // kernel points
#define DIN      64
#define DOUT     64
#define OD       45          // offset dim = NKP*3
#define ODP      48          // padded offset dim
#define KD       (NKP*DIN)   // 960
#define QPB      16          // queries per block (50000 = 3125*16 exactly)
#define NTHREADS 256
#define CHUNK    120         // kd chunk for weight staging
#define NCHUNK   (KD/CHUNK)  // 8

// Shared memory layout (in floats)
#define SM_WF    0                        // QPB*KD            = 15360
#define SM_NB    (SM_WF + QPB*KD)         // QPB*MNB*3         = 1536   (neighbor displacements)
#define SM_NI    (SM_NB + QPB*MNB*3)      // QPB*MNB (ints)    = 512
#define SM_OF    (SM_NI + QPB*MNB)        // QPB*ODP           = 768    (offset feats)
#define SM_KP    (SM_OF + QPB*ODP)        // ODP               = 48
#define SM_OV    (SM_KP + ODP)            // overlay base
#define SM_AW    SM_OV                    // 8 warps * 32 * 20 = 5120   (influence weights, [m][k] stride 20)
#define SM_DK    (SM_OV + 8*MNB*20)       // 8 warps * ODP     = 384    (deformed kernel points)
#define SM_ST    SM_OV                    // CHUNK*DOUT        = 7680   (weight stage, overlays AW/DK)
#define SM_FLOATS (SM_OV + CHUNK*DOUT)
#define SMEM_BYTES (SM_FLOATS*4)          // 103,616 bytes

// Per-query aggregation: given neighbor displacement (nbx..) for this lane's
// neighbor, kernel points kpp[45], compute influence weights then
// WF[k][d] = sum_m aw[k][m] * x[neigh[m]][d], storing into s_wf row ql.
// Each lane owns channels (2*lane, 2*lane+1).
__device__ __forceinline__ void kp_aggregate(
    float* sm, int warp, int lane, int ql,
    float nbx, float nby, float nbz,
    const float* kpp,
    const float* __restrict__ x)
{
    // influence weights: aw = max(1 - dist, 0)  (extent = 1.0)
    float* awp = sm + SM_AW + warp*(MNB*20) + lane*20;
#pragma unroll
    for (int k = 0; k < NKP; k++) {
        float dx = nbx - kpp[3*k+0];
        float dy = nby - kpp[3*k+1];
        float dz = nbz - kpp[3*k+2];
        float d  = sqrtf(fmaf(dx, dx, fmaf(dy, dy, dz*dz)));
        awp[k] = fmaxf(1.0f - d, 0.0f);
    }
    __syncwarp();

    float2 acc[NKP];
#pragma unroll
    for (int k = 0; k < NKP; k++) acc[k] = make_float2(0.f, 0.f);

    const int*   nip = (const int*)(sm + SM_NI) + ql*MNB;
    const float* awb = sm + SM_AW + warp*(MNB*20);
    const float2* x2 = (const float2*)x;

#pragma unroll 8
    for (int m = 0; m < MNB; m++) {
        float2 f = __ldg(&x2[nip[m]*(DIN/2) + lane]);   // coalesced 256B/row gather
        float av[16];
        *(float4*)(av+0)  = *(const float4*)(awb + m*20 + 0);
        *(float4*)(av+4)  = *(const float4*)(awb + m*20 + 4);
        *(float4*)(av+8)  = *(const float4*)(awb + m*20 + 8);
        *(float4*)(av+12) = *(const float4*)(awb + m*20 + 12);  // av[15] unused garbage
#pragma unroll
        for (int k = 0; k < NKP; k++) {
            acc[k].x = fmaf(av[k], f.x, acc[k].x);
            acc[k].y = fmaf(av[k], f.y, acc[k].y);
        }
    }

    float* wfr = sm + SM_WF + ql*KD;
#pragma unroll
    for (int k = 0; k < NKP; k++)
        *(float2*)(wfr + k*DIN + 2*lane) = acc[k];      // STS.64, conflict-free
    __syncwarp();
}

__global__ __launch_bounds__(NTHREADS, 2)
void kpconv_deform_fused(
    const float* __restrict__ qp,    // [N,3]
    const float* __restrict__ sp,    // [N,3]
    const int*   __restrict__ neigh, // [N,32]
    const float* __restrict__ x,     // [N,64]
    const float* __restrict__ kpts,  // [15,3]
    const float* __restrict__ ow,    // [15,64,45]
    const float* __restrict__ obias, // [45]
    const float* __restrict__ w,     // [15,64,64]
    float*       __restrict__ out)   // [N,64]
{
    extern __shared__ float sm[];
    const int tid  = threadIdx.x;
    const int lane = tid & 31;
    const int warp = tid >> 5;
    const int q0   = blockIdx.x * QPB;

    if (tid < NKP*3) sm[SM_KP + tid] = kpts[tid];
    __syncthreads();

    // ---------------- Phase 1: rigid aggregation -> WF1 ----------------
#pragma unroll
    for (int i = 0; i < 2; i++) {
        int ql = warp*2 + i;
        int q  = q0 + ql;
        float qx = qp[q*3+0], qy = qp[q*3+1], qz = qp[q*3+2];
        int   ni = neigh[q*MNB + lane];
        float nbx = sp[ni*3+0] - qx;
        float nby = sp[ni*3+1] - qy;
        float nbz = sp[ni*3+2] - qz;
        ((int*)(sm + SM_NI))[ql*MNB + lane] = ni;
        sm[SM_NB + ql*MNB*3 + lane*3 + 0] = nbx;
        sm[SM_NB + ql*MNB*3 + lane*3 + 1] = nby;
        sm[SM_NB + ql*MNB*3 + lane*3 + 2] = nbz;
        __syncwarp();
        kp_aggregate(sm, warp, lane, ql, nbx, nby, nbz, sm + SM_KP, x);
    }
    __syncthreads();

    // ---------------- Phase 2: offset GEMM (16 x 45) = WF1 (16x960) @ OW (960x45) ----------------
    {
        const bool active = (tid < 192);
        const int  ec = tid % 24;        // -> e = 2*ec, 2*ec+1  (padded to 48)
        const int  qr = tid / 24;        // 0..7 ; queries qr and qr+8
        float a00 = 0.f, a01 = 0.f, a10 = 0.f, a11 = 0.f;

        for (int c = 0; c < NCHUNK; c++) {
            __syncthreads();   // previous readers of SM_ST / phase-1 AW done
            for (int j = tid; j < CHUNK*ODP; j += NTHREADS) {
                int kk = j / ODP;
                int e  = j - kk*ODP;
                sm[SM_ST + j] = (e < OD) ? __ldg(&ow[(c*CHUNK + kk)*OD + e]) : 0.0f;
            }
            __syncthreads();
            if (active) {
                const float* w0 = sm + SM_WF + qr*KD     + c*CHUNK;
                const float* w1 = sm + SM_WF + (qr+8)*KD + c*CHUNK;
#pragma unroll 8
                for (int kk = 0; kk < CHUNK; kk++) {
                    float2 wv = *(const float2*)(sm + SM_ST + kk*ODP + 2*ec);
                    float f0 = w0[kk], f1 = w1[kk];
                    a00 = fmaf(f0, wv.x, a00); a01 = fmaf(f0, wv.y, a01);
                    a10 = fmaf(f1, wv.x, a10); a11 = fmaf(f1, wv.y, a11);
                }
            }
        }
        __syncthreads();   // all GEMM reads of WF1 done (phase 3 overwrites it)
        if (active) {
            int e = 2*ec;
            if (e < OD) {
                float b0 = obias[e];
                sm[SM_OF + qr*ODP     + e] = a00 + b0;
                sm[SM_OF + (qr+8)*ODP + e] = a10 + b0;
            }
            if (e+1 < OD) {
                float b1 = obias[e+1];
                sm[SM_OF + qr*ODP     + e+1] = a01 + b1;
                sm[SM_OF + (qr+8)*ODP + e+1] = a11 + b1;
            }
        }
    }
    __syncthreads();

    // ---------------- Phase 3: deformed aggregation -> WF2 ----------------
#pragma unroll
    for (int i = 0; i < 2; i++) {
        int ql = warp*2 + i;
        float* dk = sm + SM_DK + warp*ODP;
        // deformed kernel points: K_points + offsets  (POINT_INFLUENCE = 1.0)
        if (lane < OD)      dk[lane]      = sm[SM_KP + lane]      + sm[SM_OF + ql*ODP + lane];
        if (lane + 32 < OD) dk[lane + 32] = sm[SM_KP + lane + 32] + sm[SM_OF + ql*ODP + lane + 32];
        __syncwarp();
        float nbx = sm[SM_NB + ql*MNB*3 + lane*3 + 0];
        float nby = sm[SM_NB + ql*MNB*3 + lane*3 + 1];
        float nbz = sm[SM_NB + ql*MNB*3 + lane*3 + 2];
        kp_aggregate(sm, warp, lane, ql, nbx, nby, nbz, dk, x);
    }
    __syncthreads();

    // ---------------- Phase 4: output GEMM (16 x 64) = WF2 (16x960) @ W (960x64) ----------------
    {
        const int ec = tid & 31;     // e = 2*ec, 2*ec+1
        const int qr = tid >> 5;     // 0..7 ; queries qr and qr+8
        float a00 = 0.f, a01 = 0.f, a10 = 0.f, a11 = 0.f;

        for (int c = 0; c < NCHUNK; c++) {
            __syncthreads();
            for (int j = tid; j < CHUNK*DOUT; j += NTHREADS)
                sm[SM_ST + j] = __ldg(&w[c*CHUNK*DOUT + j]);
            __syncthreads();
            const float* w0 = sm + SM_WF + qr*KD     + c*CHUNK;
            const float* w1 = sm + SM_WF + (qr+8)*KD + c*CHUNK;
#pragma unroll 8
            for (int kk = 0; kk < CHUNK; kk++) {
                float2 wv = *(const float2*)(sm + SM_ST + kk*DOUT + 2*ec);
                float f0 = w0[kk], f1 = w1[kk];
                a00 = fmaf(f0, wv.x, a00); a01 = fmaf(f0, wv.y, a01);
                a10 = fmaf(f1, wv.x, a10); a11 = fmaf(f1, wv.y, a11);
            }
        }

        float2* o2 = (float2*)out;
        o2[(q0 + qr)*(DOUT/2)     + ec] = make_float2(a00, a01);
        o2[(q0 + qr + 8)*(DOUT/2) + ec] = make_float2(a10, a11);
    }
}

extern "C" void kernel_launch(void* const* d_in, const int* in_sizes, int n_in,
                              void* d_out, int out_size)
{
    const float* qp    = (const float*)d_in[0];
    const float* sp    = (const float*)d_in[1];
    const int*   neigh = (const int*)  d_in[2];
    const float* x     = (const float*)d_in[3];
    const float* kpts  = (const float*)d_in[4];
    const float* ow    = (const float*)d_in[5];
    const float* obias = (const float*)d_in[6];
    const float* w     = (const float*)d_in[7];
    float* out = (float*)d_out;

    cudaFuncSetAttribute(kpconv_deform_fused,
                         cudaFuncAttributeMaxDynamicSharedMemorySize, SMEM_BYTES);

    kpconv_deform_fused<<<NQ/QPB, NTHREADS, SMEM_BYTES>>>(
        qp, sp, neigh, x, kpts, ow, obias, w, out);
}

// round 3
// speedup vs baseline: 1.2340x; 1.2340x over previous
#include <cuda_runtime.h>
#include <cstdint>

#define NQ       50000
#define MNB      32
#define NKP      15
#define DIN      64
#define DOUT     64
#define OD       45
#define ODP      48
#define KD       960          // NKP*DIN
#define QPB      8            // queries per block (50000 = 6250*8)
#define NTHREADS 256
#define KSLICE   120          // KD / 8 warps

// ---------------- shared memory layout (floats) ----------------
#define SM_WFD   0                         // QPB * 2*KD (duplicated features) = 15360
#define SM_NB    (SM_WFD + QPB*2*KD)       // QPB*MNB*3 = 768
#define SM_NI    (SM_NB  + QPB*MNB*3)      // QPB*MNB   = 256 (ints)
#define SM_OF    (SM_NI  + QPB*MNB)        // QPB*ODP   = 384
#define SM_KP    (SM_OF  + QPB*ODP)        // ODP       = 48
#define SM_DK    (SM_KP  + ODP)            // QPB*ODP   = 384
#define SM_AWD   (SM_DK  + QPB*ODP)        // 8 warps * 32 * 36 = 9216 (dup aw; overlaid by GEMM partials)
#define SM_PART  SM_AWD
#define SM_TOT   (SM_AWD + 8*32*36)
#define SMEM_BYTES (SM_TOT*4)              // 105,664 bytes -> 2 blocks/SM

// zero-padded offset weights [960][48]
__device__ float g_owpad[KD*ODP];

__global__ void prep_owpad(const float* __restrict__ ow)
{
    int i = blockIdx.x*blockDim.x + threadIdx.x;
    if (i < KD*ODP) {
        int kk = i / ODP, e = i - kk*ODP;
        g_owpad[i] = (e < OD) ? ow[kk*OD + e] : 0.0f;
    }
}

// packed fp32x2 FMA (Blackwell FFMA2) — d = a*b + c lanewise on packed pairs
__device__ __forceinline__ uint64_t ffma2(uint64_t a, uint64_t b, uint64_t c)
{
    uint64_t d;
    asm("fma.rn.f32x2 %0, %1, %2, %3;" : "=l"(d) : "l"(a), "l"(b), "l"(c));
    return d;
}

// Per-warp aggregation for query q==warp. Lane owns channels (2*lane, 2*lane+1).
// Writes WF duplicated: wfd[q][2*kd + {0,1}] = wf[q][kd].
__device__ __forceinline__ void kp_aggregate(
    float* sm, int warp, int lane,
    float nbx, float nby, float nbz,
    const float* kpp,                 // 45 floats in shared
    const float* __restrict__ x)
{
    // influence weights, stored duplicated (w,w) per k; row stride 36 floats
    float* awr = sm + SM_AWD + warp*1152 + lane*36;
#pragma unroll
    for (int k = 0; k < NKP; k++) {
        float dx = nbx - kpp[3*k+0];
        float dy = nby - kpp[3*k+1];
        float dz = nbz - kpp[3*k+2];
        float d  = sqrtf(fmaf(dx, dx, fmaf(dy, dy, dz*dz)));
        float wv = fmaxf(1.0f - d, 0.0f);
        *(float2*)(awr + 2*k) = make_float2(wv, wv);
    }
    __syncwarp();

    uint64_t acc[NKP];
#pragma unroll
    for (int k = 0; k < NKP; k++) acc[k] = 0ull;

    const int*   nip = (const int*)(sm + SM_NI) + warp*MNB;
    const float* awb = sm + SM_AWD + warp*1152;

#pragma unroll 4
    for (int m = 0; m < MNB; m++) {
        int n = nip[m];
        uint64_t f2 = *(const uint64_t*)(x + n*DIN + 2*lane);   // packed (c0,c1), LDG.64 coalesced
        const ulonglong2* ar = (const ulonglong2*)(awb + m*36); // dup (w,w) pairs, broadcast LDS.128
        ulonglong2 a0 = ar[0], a1 = ar[1], a2 = ar[2], a3 = ar[3];
        ulonglong2 a4 = ar[4], a5 = ar[5], a6 = ar[6], a7 = ar[7];
        acc[0]  = ffma2(a0.x, f2, acc[0]);
        acc[1]  = ffma2(a0.y, f2, acc[1]);
        acc[2]  = ffma2(a1.x, f2, acc[2]);
        acc[3]  = ffma2(a1.y, f2, acc[3]);
        acc[4]  = ffma2(a2.x, f2, acc[4]);
        acc[5]  = ffma2(a2.y, f2, acc[5]);
        acc[6]  = ffma2(a3.x, f2, acc[6]);
        acc[7]  = ffma2(a3.y, f2, acc[7]);
        acc[8]  = ffma2(a4.x, f2, acc[8]);
        acc[9]  = ffma2(a4.y, f2, acc[9]);
        acc[10] = ffma2(a5.x, f2, acc[10]);
        acc[11] = ffma2(a5.y, f2, acc[11]);
        acc[12] = ffma2(a6.x, f2, acc[12]);
        acc[13] = ffma2(a6.y, f2, acc[13]);
        acc[14] = ffma2(a7.x, f2, acc[14]);
    }

    // store duplicated features: one STS.128 per k, conflict-free
    float* wr = sm + SM_WFD + warp*(2*KD);
#pragma unroll
    for (int k = 0; k < NKP; k++) {
        float lo = __uint_as_float((uint32_t)acc[k]);
        float hi = __uint_as_float((uint32_t)(acc[k] >> 32));
        *(float4*)(wr + k*128 + 4*lane) = make_float4(lo, lo, hi, hi);
    }
}

__global__ __launch_bounds__(NTHREADS, 2)
void kpconv_deform_fused(
    const float* __restrict__ qp,    // [N,3]
    const float* __restrict__ sp,    // [N,3]
    const int*   __restrict__ neigh, // [N,32]
    const float* __restrict__ x,     // [N,64]
    const float* __restrict__ kpts,  // [15,3]
    const float* __restrict__ obias, // [45]
    const float* __restrict__ w,     // [960,64]
    float*       __restrict__ out)   // [N,64]
{
    extern __shared__ float sm[];
    const int tid  = threadIdx.x;
    const int lane = tid & 31;
    const int warp = tid >> 5;
    const int q0   = blockIdx.x * QPB;
    const int q    = q0 + warp;

    if (tid < OD) sm[SM_KP + tid] = kpts[tid];

    // neighbor geometry (one query per warp)
    float nbx, nby, nbz;
    {
        float qx = qp[q*3+0], qy = qp[q*3+1], qz = qp[q*3+2];
        int   ni = neigh[q*MNB + lane];
        nbx = sp[ni*3+0] - qx;
        nby = sp[ni*3+1] - qy;
        nbz = sp[ni*3+2] - qz;
        ((int*)(sm + SM_NI))[warp*MNB + lane] = ni;
        sm[SM_NB + warp*96 + lane*3 + 0] = nbx;
        sm[SM_NB + warp*96 + lane*3 + 1] = nby;
        sm[SM_NB + warp*96 + lane*3 + 2] = nbz;
    }
    __syncthreads();

    // -------- Phase 1: rigid aggregation -> WF1 (duplicated) --------
    kp_aggregate(sm, warp, lane, nbx, nby, nbz, sm + SM_KP, x);
    __syncthreads();

    // -------- Phase 2: offset GEMM  OF[8][45] = WF1[8][960] @ OWpad[960][48] --------
    {
        uint64_t acc[QPB];
#pragma unroll
        for (int qi = 0; qi < QPB; qi++) acc[qi] = 0ull;
        if (lane < 24) {
            const int kk0 = warp * KSLICE;
#pragma unroll 2
            for (int kk = kk0; kk < kk0 + KSLICE; kk += 2) {
                uint64_t wa = *(const uint64_t*)(g_owpad + kk*ODP     + 2*lane);  // (e0,e1) of row kk
                uint64_t wb = *(const uint64_t*)(g_owpad + (kk+1)*ODP + 2*lane);
#pragma unroll
                for (int qi = 0; qi < QPB; qi++) {
                    ulonglong2 f = *(const ulonglong2*)(sm + SM_WFD + qi*(2*KD) + 2*kk); // (f_kk dup, f_kk+1 dup)
                    acc[qi] = ffma2(f.x, wa, acc[qi]);
                    acc[qi] = ffma2(f.y, wb, acc[qi]);
                }
            }
#pragma unroll
            for (int qi = 0; qi < QPB; qi++)
                *(uint64_t*)(sm + SM_PART + warp*384 + qi*48 + 2*lane) = acc[qi];
        }
    }
    __syncthreads();

    // reduce 8 k-slices -> OF (+bias); padded channels come out 0
    if (tid < 192) {
        int qi = tid / 24, ep = tid % 24, e = 2*ep;
        float sx = 0.f, sy = 0.f;
#pragma unroll
        for (int ws = 0; ws < 8; ws++) {
            float2 p = *(const float2*)(sm + SM_PART + ws*384 + qi*48 + e);
            sx += p.x; sy += p.y;
        }
        sx += (e   < OD) ? obias[e]   : 0.f;
        sy += (e+1 < OD) ? obias[e+1] : 0.f;
        *(float2*)(sm + SM_OF + qi*ODP + e) = make_float2(sx, sy);
    }
    __syncthreads();

    // -------- Phase 3: deformed kernel points + aggregation -> WF2 --------
    for (int j = lane; j < OD; j += 32)
        sm[SM_DK + warp*ODP + j] = sm[SM_KP + j] + sm[SM_OF + warp*ODP + j];
    __syncwarp();
    {
        float bx = sm[SM_NB + warp*96 + lane*3 + 0];
        float by = sm[SM_NB + warp*96 + lane*3 + 1];
        float bz = sm[SM_NB + warp*96 + lane*3 + 2];
        kp_aggregate(sm, warp, lane, bx, by, bz, sm + SM_DK + warp*ODP, x);
    }
    __syncthreads();

    // -------- Phase 4: output GEMM  out[8][64] = WF2[8][960] @ W[960][64] --------
    {
        uint64_t acc[QPB];
#pragma unroll
        for (int qi = 0; qi < QPB; qi++) acc[qi] = 0ull;
        const int kk0 = warp * KSLICE;
#pragma unroll 2
        for (int kk = kk0; kk < kk0 + KSLICE; kk += 2) {
            uint64_t wa = *(const uint64_t*)(w + kk*DOUT     + 2*lane);
            uint64_t wb = *(const uint64_t*)(w + (kk+1)*DOUT + 2*lane);
#pragma unroll
            for (int qi = 0; qi < QPB; qi++) {
                ulonglong2 f = *(const ulonglong2*)(sm + SM_WFD + qi*(2*KD) + 2*kk);
                acc[qi] = ffma2(f.x, wa, acc[qi]);
                acc[qi] = ffma2(f.y, wb, acc[qi]);
            }
        }
#pragma unroll
        for (int qi = 0; qi < QPB; qi++)
            *(uint64_t*)(sm + SM_PART + warp*512 + qi*64 + 2*lane) = acc[qi];
    }
    __syncthreads();

    // reduce 8 k-slices -> global out
    {
        int qi = tid >> 5, e = (tid & 31) * 2;
        float sx = 0.f, sy = 0.f;
#pragma unroll
        for (int ws = 0; ws < 8; ws++) {
            float2 p = *(const float2*)(sm + SM_PART + ws*512 + qi*64 + e);
            sx += p.x; sy += p.y;
        }
        *(float2*)(out + (q0 + qi)*DOUT + e) = make_float2(sx, sy);
    }
}

extern "C" void kernel_launch(void* const* d_in, const int* in_sizes, int n_in,
                              void* d_out, int out_size)
{
    const float* qp    = (const float*)d_in[0];
    const float* sp    = (const float*)d_in[1];
    const int*   neigh = (const int*)  d_in[2];
    const float* x     = (const float*)d_in[3];
    const float* kpts  = (const float*)d_in[4];
    const float* ow    = (const float*)d_in[5];
    const float* obias = (const float*)d_in[6];
    const float* w     = (const float*)d_in[7];
    float* out = (float*)d_out;

    prep_owpad<<<(KD*ODP + 255)/256, 256>>>(ow);

    cudaFuncSetAttribute(kpconv_deform_fused,
                         cudaFuncAttributeMaxDynamicSharedMemorySize, SMEM_BYTES);

    kpconv_deform_fused<<<NQ/QPB, NTHREADS, SMEM_BYTES>>>(
        qp, sp, neigh, x, kpts, obias, w, out);
}

// round 5
// speedup vs baseline: 1.4117x; 1.1440x over previous
#include <cuda_runtime.h>
#include <cstdint>

#define NQ       50000
#define MNB      32
#define NKP      15
#define DIN      64
#define DOUT     64
#define OD       45
#define ODP      48
#define KD       960
#define QPB      8
#define NTHREADS 256
#define KSL      60          // k per slice; 16 slices cover KD

// ---------------- shared memory layout (floats) ----------------
#define SM_WFD 0                        // QPB*2*KD = 15360 (dup features)
#define SM_OF  (SM_WFD + QPB*2*KD)      // QPB*ODP  = 384
#define SM_KP  (SM_OF + QPB*ODP)        // 48
#define SM_DK  (SM_KP + ODP)            // QPB*ODP  = 384
#define SM_OV  (SM_DK + QPB*ODP)        // overlay: AWD (9216) / P4 (8192) / P2 (6144)
#define SM_AWD SM_OV
#define SM_P4  SM_OV
#define SM_P2  SM_OV
#define SM_TOT (SM_OV + 8*1152)
#define SMEM_BYTES (SM_TOT*4)           // 101,568 B -> 2 blocks/SM

// zero-padded offset weights [960][48]
__device__ float g_owpad[KD*ODP];

__global__ void prep_owpad(const float* __restrict__ ow)
{
    int i = blockIdx.x*blockDim.x + threadIdx.x;
    if (i < KD*ODP) {
        int kk = i / ODP, e = i - kk*ODP;
        g_owpad[i] = (e < OD) ? ow[kk*OD + e] : 0.0f;
    }
}

__device__ __forceinline__ uint64_t ffma2(uint64_t a, uint64_t b, uint64_t c)
{
    uint64_t d;
    asm("fma.rn.f32x2 %0, %1, %2, %3;" : "=l"(d) : "l"(a), "l"(b), "l"(c));
    return d;
}
__device__ __forceinline__ uint64_t fadd2(uint64_t a, uint64_t b)
{
    uint64_t d;
    asm("add.rn.f32x2 %0, %1, %2;" : "=l"(d) : "l"(a), "l"(b));
    return d;
}

// Aggregation for query q == warp. Lane (h = lane>>4, j = lane&15):
// half h processes neighbors m = 2s+h; j owns channel quad 4j..4j+3.
// Output written to WFD (duplicated layout) after cross-half shfl reduction.
__device__ __forceinline__ void kp_aggregate(
    float* sm, int warp, int lane, int h, int j,
    float nbx, float nby, float nbz, int ni,
    const float* kpp,
    const float* __restrict__ x)
{
    // influence weights for this lane's own neighbor (m = lane), stored dup
    float* awr = sm + SM_AWD + warp*1152 + lane*36;
#pragma unroll
    for (int k = 0; k < NKP; k++) {
        float dx = nbx - kpp[3*k+0];
        float dy = nby - kpp[3*k+1];
        float dz = nbz - kpp[3*k+2];
        float d  = sqrtf(fmaf(dx, dx, fmaf(dy, dy, dz*dz)));
        float wv = fmaxf(1.0f - d, 0.0f);
        *(float2*)(awr + 2*k) = make_float2(wv, wv);
    }
    __syncwarp();

    uint64_t alo[NKP], ahi[NKP];
#pragma unroll
    for (int k = 0; k < NKP; k++) { alo[k] = 0ull; ahi[k] = 0ull; }

    const float* awb = sm + SM_AWD + warp*1152;

#pragma unroll 4
    for (int s = 0; s < 16; s++) {
        int m = 2*s + h;
        int n = __shfl_sync(0xffffffffu, ni, m);
        ulonglong2 f2 = *(const ulonglong2*)(x + n*DIN + 4*j);  // (c0,c1),(c2,c3)
        const ulonglong2* ar = (const ulonglong2*)(awb + m*36);
        {
            ulonglong2 a0 = ar[0], a1 = ar[1], a2 = ar[2], a3 = ar[3];
            alo[0] = ffma2(a0.x, f2.x, alo[0]); ahi[0] = ffma2(a0.x, f2.y, ahi[0]);
            alo[1] = ffma2(a0.y, f2.x, alo[1]); ahi[1] = ffma2(a0.y, f2.y, ahi[1]);
            alo[2] = ffma2(a1.x, f2.x, alo[2]); ahi[2] = ffma2(a1.x, f2.y, ahi[2]);
            alo[3] = ffma2(a1.y, f2.x, alo[3]); ahi[3] = ffma2(a1.y, f2.y, ahi[3]);
            alo[4] = ffma2(a2.x, f2.x, alo[4]); ahi[4] = ffma2(a2.x, f2.y, ahi[4]);
            alo[5] = ffma2(a2.y, f2.x, alo[5]); ahi[5] = ffma2(a2.y, f2.y, ahi[5]);
            alo[6] = ffma2(a3.x, f2.x, alo[6]); ahi[6] = ffma2(a3.x, f2.y, ahi[6]);
            alo[7] = ffma2(a3.y, f2.x, alo[7]); ahi[7] = ffma2(a3.y, f2.y, ahi[7]);
        }
        {
            ulonglong2 a4 = ar[4], a5 = ar[5], a6 = ar[6], a7 = ar[7];
            alo[8]  = ffma2(a4.x, f2.x, alo[8]);  ahi[8]  = ffma2(a4.x, f2.y, ahi[8]);
            alo[9]  = ffma2(a4.y, f2.x, alo[9]);  ahi[9]  = ffma2(a4.y, f2.y, ahi[9]);
            alo[10] = ffma2(a5.x, f2.x, alo[10]); ahi[10] = ffma2(a5.x, f2.y, ahi[10]);
            alo[11] = ffma2(a5.y, f2.x, alo[11]); ahi[11] = ffma2(a5.y, f2.y, ahi[11]);
            alo[12] = ffma2(a6.x, f2.x, alo[12]); ahi[12] = ffma2(a6.x, f2.y, ahi[12]);
            alo[13] = ffma2(a6.y, f2.x, alo[13]); ahi[13] = ffma2(a6.y, f2.y, ahi[13]);
            alo[14] = ffma2(a7.x, f2.x, alo[14]); ahi[14] = ffma2(a7.x, f2.y, ahi[14]);
        }
    }

    // cross-half reduction: h=0 finalizes (e4j,e4j+1), h=1 finalizes (e4j+2,e4j+3)
    float* wr = sm + SM_WFD + warp*(2*KD);
#pragma unroll
    for (int k = 0; k < NKP; k++) {
        unsigned long long send = h ? (unsigned long long)alo[k] : (unsigned long long)ahi[k];
        unsigned long long recv = __shfl_xor_sync(0xffffffffu, send, 16);
        uint64_t mine = h ? ahi[k] : alo[k];
        uint64_t tot  = fadd2(mine, (uint64_t)recv);
        float lo = __uint_as_float((uint32_t)tot);
        float hi = __uint_as_float((uint32_t)(tot >> 32));
        *(float4*)(wr + k*128 + 8*j + 4*h) = make_float4(lo, lo, hi, hi);
    }
}

__global__ __launch_bounds__(NTHREADS, 2)
void kpconv_deform_fused(
    const float* __restrict__ qp,    // [N,3]
    const float* __restrict__ sp,    // [N,3]
    const int*   __restrict__ neigh, // [N,32]
    const float* __restrict__ x,     // [N,64]
    const float* __restrict__ kpts,  // [15,3]
    const float* __restrict__ obias, // [45]
    const float* __restrict__ w,     // [960,64]
    float*       __restrict__ out)   // [N,64]
{
    extern __shared__ float sm[];
    const int tid  = threadIdx.x;
    const int lane = tid & 31;
    const int warp = tid >> 5;
    const int h    = (lane >> 4) & 1;
    const int j    = lane & 15;
    const int q0   = blockIdx.x * QPB;
    const int q    = q0 + warp;

    if (tid < OD) sm[SM_KP + tid] = kpts[tid];

    // neighbor geometry, kept in registers (lane = its own neighbor m)
    float qx = qp[q*3+0], qy = qp[q*3+1], qz = qp[q*3+2];
    int   ni = neigh[q*MNB + lane];
    float nbx = sp[ni*3+0] - qx;
    float nby = sp[ni*3+1] - qy;
    float nbz = sp[ni*3+2] - qz;
    __syncthreads();

    // -------- Phase 1: rigid aggregation -> WF1 --------
    kp_aggregate(sm, warp, lane, h, j, nbx, nby, nbz, ni, sm + SM_KP, x);
    __syncthreads();

    // -------- Phase 2: offset GEMM  OF[8][48] = WF1[8][960] @ OWpad[960][48] --------
    {
        const int slice = warp*2 + h;        // 0..15
        const int kk0   = slice * KSL;
        uint64_t aclo[QPB], achi[QPB];
#pragma unroll
        for (int qi = 0; qi < QPB; qi++) { aclo[qi] = 0ull; achi[qi] = 0ull; }
        if (j < 12) {
            for (int kk = kk0; kk < kk0 + KSL; kk += 2) {
                ulonglong2 wA = *(const ulonglong2*)(g_owpad + kk*ODP     + 4*j);
                ulonglong2 wB = *(const ulonglong2*)(g_owpad + (kk+1)*ODP + 4*j);
#pragma unroll
                for (int qi = 0; qi < QPB; qi++) {
                    ulonglong2 f = *(const ulonglong2*)(sm + SM_WFD + qi*(2*KD) + 2*kk);
                    aclo[qi] = ffma2(f.x, wA.x, aclo[qi]);
                    achi[qi] = ffma2(f.x, wA.y, achi[qi]);
                    aclo[qi] = ffma2(f.y, wB.x, aclo[qi]);
                    achi[qi] = ffma2(f.y, wB.y, achi[qi]);
                }
            }
#pragma unroll
            for (int qi = 0; qi < QPB; qi++)
                *(ulonglong2*)(sm + SM_P2 + slice*384 + qi*48 + 4*j) =
                    make_ulonglong2(aclo[qi], achi[qi]);
        }
    }
    __syncthreads();

    // reduce 16 k-slices -> OF (+bias)
    if (tid < 192) {
        int qi = tid / 24, ep = tid % 24, e = 2*ep;
        float sx = 0.f, sy = 0.f;
#pragma unroll
        for (int s = 0; s < 16; s++) {
            float2 p = *(const float2*)(sm + SM_P2 + s*384 + qi*48 + e);
            sx += p.x; sy += p.y;
        }
        sx += (e   < OD) ? obias[e]   : 0.f;
        sy += (e+1 < OD) ? obias[e+1] : 0.f;
        *(float2*)(sm + SM_OF + qi*ODP + e) = make_float2(sx, sy);
    }
    __syncthreads();

    // -------- Phase 3: deformed kernel points + aggregation -> WF2 --------
    for (int t2 = lane; t2 < OD; t2 += 32)
        sm[SM_DK + warp*ODP + t2] = sm[SM_KP + t2] + sm[SM_OF + warp*ODP + t2];
    __syncwarp();
    kp_aggregate(sm, warp, lane, h, j, nbx, nby, nbz, ni, sm + SM_DK + warp*ODP, x);
    __syncthreads();

    // -------- Phase 4: output GEMM  out[8][64] = WF2[8][960] @ W[960][64] --------
    {
        const int slice = warp*2 + h;
        const int kk0   = slice * KSL;
        uint64_t aclo[QPB], achi[QPB];
#pragma unroll
        for (int qi = 0; qi < QPB; qi++) { aclo[qi] = 0ull; achi[qi] = 0ull; }
        for (int kk = kk0; kk < kk0 + KSL; kk += 2) {
            ulonglong2 wA = *(const ulonglong2*)(w + kk*DOUT     + 4*j);
            ulonglong2 wB = *(const ulonglong2*)(w + (kk+1)*DOUT + 4*j);
#pragma unroll
            for (int qi = 0; qi < QPB; qi++) {
                ulonglong2 f = *(const ulonglong2*)(sm + SM_WFD + qi*(2*KD) + 2*kk);
                aclo[qi] = ffma2(f.x, wA.x, aclo[qi]);
                achi[qi] = ffma2(f.x, wA.y, achi[qi]);
                aclo[qi] = ffma2(f.y, wB.x, aclo[qi]);
                achi[qi] = ffma2(f.y, wB.y, achi[qi]);
            }
        }
#pragma unroll
        for (int qi = 0; qi < QPB; qi++)
            *(ulonglong2*)(sm + SM_P4 + slice*512 + qi*64 + 4*j) =
                make_ulonglong2(aclo[qi], achi[qi]);
    }
    __syncthreads();

    // reduce 16 k-slices -> global out
    {
        int qi = tid >> 5, e = (tid & 31) * 2;
        float sx = 0.f, sy = 0.f;
#pragma unroll
        for (int s = 0; s < 16; s++) {
            float2 p = *(const float2*)(sm + SM_P4 + s*512 + qi*64 + e);
            sx += p.x; sy += p.y;
        }
        *(float2*)(out + (q0 + qi)*DOUT + e) = make_float2(sx, sy);
    }
}

extern "C" void kernel_launch(void* const* d_in, const int* in_sizes, int n_in,
                              void* d_out, int out_size)
{
    const float* qp    = (const float*)d_in[0];
    const float* sp    = (const float*)d_in[1];
    const int*   neigh = (const int*)  d_in[2];
    const float* x     = (const float*)d_in[3];
    const float* kpts  = (const float*)d_in[4];
    const float* ow    = (const float*)d_in[5];
    const float* obias = (const float*)d_in[6];
    const float* w     = (const float*)d_in[7];
    float* out = (float*)d_out;

    prep_owpad<<<(KD*ODP + 255)/256, 256>>>(ow);

    cudaFuncSetAttribute(kpconv_deform_fused,
                         cudaFuncAttributeMaxDynamicSharedMemorySize, SMEM_BYTES);

    kpconv_deform_fused<<<NQ/QPB, NTHREADS, SMEM_BYTES>>>(
        qp, sp, neigh, x, kpts, obias, w, out);
}

// round 6
// speedup vs baseline: 1.6267x; 1.1523x over previous
#include <cuda_runtime.h>
#include <cstdint>

#define NQ       50000
#define MNB      32
#define NKP      15
#define DIN      64
#define DOUT     64
#define OD       45
#define ODP      48
#define KD       960
#define QPB      8
#define NTHREADS 256
#define KSL      60          // k per GEMM slice; 16 slices cover KD

// ---------------- shared memory layout (floats) ----------------
#define SM_WF  0                        // QPB*KD = 7680 (non-dup features)
#define SM_OF  (SM_WF + QPB*KD)         // QPB*ODP = 384
#define SM_KP  (SM_OF + QPB*ODP)        // 48
#define SM_DK  (SM_KP + ODP)            // QPB*ODP = 384
#define SM_OV  (SM_DK + QPB*ODP)        // overlay: AWD 9216 / P2 6144 / P4 8192
#define SM_AWD SM_OV
#define SM_P2  SM_OV
#define SM_P4  SM_OV
#define SM_TOT (SM_OV + 8*1152)
#define SMEM_BYTES (SM_TOT*4)           // 70,848 B -> 3 blocks/SM

// zero-padded offset weights [960][48]
__device__ float g_owpad[KD*ODP];

__global__ void prep_owpad(const float* __restrict__ ow)
{
    int i = blockIdx.x*blockDim.x + threadIdx.x;
    if (i < KD*ODP) {
        int kk = i / ODP, e = i - kk*ODP;
        g_owpad[i] = (e < OD) ? ow[kk*OD + e] : 0.0f;
    }
}

__device__ __forceinline__ uint64_t ffma2(uint64_t a, uint64_t b, uint64_t c)
{
    uint64_t d;
    asm("fma.rn.f32x2 %0, %1, %2, %3;" : "=l"(d) : "l"(a), "l"(b), "l"(c));
    return d;
}
__device__ __forceinline__ uint64_t dup2(float v)
{
    uint64_t d;
    asm("mov.b64 %0, {%1, %1};" : "=l"(d) : "f"(v));
    return d;
}

// Aggregation for query q == warp. Lane owns channel pair (2*lane, 2*lane+1).
// All lanes walk the full 32-neighbor loop (uniform m -> broadcast aw reads,
// coalesced LDG.64 feature rows). Non-dup WF store: STS.64 conflict-free.
__device__ __forceinline__ void kp_aggregate(
    float* sm, int warp, int lane,
    float nbx, float nby, float nbz, int ni,
    const float* kpp,
    const float* __restrict__ x)
{
    // influence weights for this lane's own neighbor (m = lane), stored dup (w,w)
    float* awr = sm + SM_AWD + warp*1152 + lane*36;
#pragma unroll
    for (int k = 0; k < NKP; k++) {
        float dx = nbx - kpp[3*k+0];
        float dy = nby - kpp[3*k+1];
        float dz = nbz - kpp[3*k+2];
        float d  = sqrtf(fmaf(dx, dx, fmaf(dy, dy, dz*dz)));
        float wv = fmaxf(1.0f - d, 0.0f);
        *(float2*)(awr + 2*k) = make_float2(wv, wv);
    }
    __syncwarp();

    uint64_t acc[NKP];
#pragma unroll
    for (int k = 0; k < NKP; k++) acc[k] = 0ull;

    const float* awb = sm + SM_AWD + warp*1152;

#pragma unroll 4
    for (int m = 0; m < MNB; m++) {
        int n = __shfl_sync(0xffffffffu, ni, m);
        uint64_t f2 = *(const uint64_t*)(x + n*DIN + 2*lane);   // (c0,c1) packed
        const ulonglong2* ar = (const ulonglong2*)(awb + m*36); // dup (w,w) pairs
        {
            ulonglong2 a0 = ar[0], a1 = ar[1], a2 = ar[2], a3 = ar[3];
            acc[0] = ffma2(a0.x, f2, acc[0]);
            acc[1] = ffma2(a0.y, f2, acc[1]);
            acc[2] = ffma2(a1.x, f2, acc[2]);
            acc[3] = ffma2(a1.y, f2, acc[3]);
            acc[4] = ffma2(a2.x, f2, acc[4]);
            acc[5] = ffma2(a2.y, f2, acc[5]);
            acc[6] = ffma2(a3.x, f2, acc[6]);
            acc[7] = ffma2(a3.y, f2, acc[7]);
        }
        {
            ulonglong2 a4 = ar[4], a5 = ar[5], a6 = ar[6], a7 = ar[7];
            acc[8]  = ffma2(a4.x, f2, acc[8]);
            acc[9]  = ffma2(a4.y, f2, acc[9]);
            acc[10] = ffma2(a5.x, f2, acc[10]);
            acc[11] = ffma2(a5.y, f2, acc[11]);
            acc[12] = ffma2(a6.x, f2, acc[12]);
            acc[13] = ffma2(a6.y, f2, acc[13]);
            acc[14] = ffma2(a7.x, f2, acc[14]);
        }
    }

    // non-dup WF store: WF[q][k*64 + 2*lane] = acc[k] (STS.64, 2 wf per k)
    float* wr = sm + SM_WF + warp*KD;
#pragma unroll
    for (int k = 0; k < NKP; k++)
        *(uint64_t*)(wr + k*DIN + 2*lane) = acc[k];
}

__global__ __launch_bounds__(NTHREADS, 3)
void kpconv_deform_fused(
    const float* __restrict__ qp,    // [N,3]
    const float* __restrict__ sp,    // [N,3]
    const int*   __restrict__ neigh, // [N,32]
    const float* __restrict__ x,     // [N,64]
    const float* __restrict__ kpts,  // [15,3]
    const float* __restrict__ obias, // [45]
    const float* __restrict__ w,     // [960,64]
    float*       __restrict__ out)   // [N,64]
{
    extern __shared__ float sm[];
    const int tid  = threadIdx.x;
    const int lane = tid & 31;
    const int warp = tid >> 5;
    const int h    = (lane >> 4) & 1;
    const int j    = lane & 15;
    const int q0   = blockIdx.x * QPB;
    const int q    = q0 + warp;

    if (tid < OD) sm[SM_KP + tid] = kpts[tid];

    // neighbor geometry, registers only (lane = its own neighbor m)
    float qx = qp[q*3+0], qy = qp[q*3+1], qz = qp[q*3+2];
    int   ni = neigh[q*MNB + lane];
    float nbx = sp[ni*3+0] - qx;
    float nby = sp[ni*3+1] - qy;
    float nbz = sp[ni*3+2] - qz;
    __syncthreads();

    // -------- Phase 1: rigid aggregation -> WF1 --------
    kp_aggregate(sm, warp, lane, nbx, nby, nbz, ni, sm + SM_KP, x);
    __syncthreads();

    // -------- Phase 2: offset GEMM  OF[8][48] = WF1[8][960] @ OWpad[960][48] --------
    {
        const int slice = warp*2 + h;        // 0..15
        const int kk0   = slice * KSL;
        uint64_t aclo[QPB], achi[QPB];
#pragma unroll
        for (int qi = 0; qi < QPB; qi++) { aclo[qi] = 0ull; achi[qi] = 0ull; }
        if (j < 12) {
            for (int kk = kk0; kk < kk0 + KSL; kk += 2) {
                ulonglong2 wA = *(const ulonglong2*)(g_owpad + kk*ODP     + 4*j);
                ulonglong2 wB = *(const ulonglong2*)(g_owpad + (kk+1)*ODP + 4*j);
#pragma unroll
                for (int qi = 0; qi < QPB; qi++) {
                    float2 f = *(const float2*)(sm + SM_WF + qi*KD + kk);  // broadcast LDS.64
                    uint64_t dx = dup2(f.x), dy = dup2(f.y);
                    aclo[qi] = ffma2(dx, wA.x, aclo[qi]);
                    achi[qi] = ffma2(dx, wA.y, achi[qi]);
                    aclo[qi] = ffma2(dy, wB.x, aclo[qi]);
                    achi[qi] = ffma2(dy, wB.y, achi[qi]);
                }
            }
        }
        __syncthreads();   // WF1 reads done before P2 overlay reuse? (P2 overlays AWD, not WF)
        if (j < 12) {
#pragma unroll
            for (int qi = 0; qi < QPB; qi++)
                *(ulonglong2*)(sm + SM_P2 + slice*384 + qi*48 + 4*j) =
                    make_ulonglong2(aclo[qi], achi[qi]);
        }
    }
    __syncthreads();

    // reduce 16 k-slices -> OF (+bias)
    if (tid < 192) {
        int qi = tid / 24, ep = tid % 24, e = 2*ep;
        float sx = 0.f, sy = 0.f;
#pragma unroll
        for (int s = 0; s < 16; s++) {
            float2 p = *(const float2*)(sm + SM_P2 + s*384 + qi*48 + e);
            sx += p.x; sy += p.y;
        }
        sx += (e   < OD) ? obias[e]   : 0.f;
        sy += (e+1 < OD) ? obias[e+1] : 0.f;
        *(float2*)(sm + SM_OF + qi*ODP + e) = make_float2(sx, sy);
    }
    __syncthreads();

    // -------- Phase 3: deformed kernel points + aggregation -> WF2 --------
    for (int t2 = lane; t2 < OD; t2 += 32)
        sm[SM_DK + warp*ODP + t2] = sm[SM_KP + t2] + sm[SM_OF + warp*ODP + t2];
    __syncwarp();
    kp_aggregate(sm, warp, lane, nbx, nby, nbz, ni, sm + SM_DK + warp*ODP, x);
    __syncthreads();

    // -------- Phase 4: output GEMM  out[8][64] = WF2[8][960] @ W[960][64] --------
    {
        const int slice = warp*2 + h;
        const int kk0   = slice * KSL;
        uint64_t aclo[QPB], achi[QPB];
#pragma unroll
        for (int qi = 0; qi < QPB; qi++) { aclo[qi] = 0ull; achi[qi] = 0ull; }
        for (int kk = kk0; kk < kk0 + KSL; kk += 2) {
            ulonglong2 wA = *(const ulonglong2*)(w + kk*DOUT     + 4*j);
            ulonglong2 wB = *(const ulonglong2*)(w + (kk+1)*DOUT + 4*j);
#pragma unroll
            for (int qi = 0; qi < QPB; qi++) {
                float2 f = *(const float2*)(sm + SM_WF + qi*KD + kk);
                uint64_t dx = dup2(f.x), dy = dup2(f.y);
                aclo[qi] = ffma2(dx, wA.x, aclo[qi]);
                achi[qi] = ffma2(dx, wA.y, achi[qi]);
                aclo[qi] = ffma2(dy, wB.x, aclo[qi]);
                achi[qi] = ffma2(dy, wB.y, achi[qi]);
            }
        }
#pragma unroll
        for (int qi = 0; qi < QPB; qi++)
            *(ulonglong2*)(sm + SM_P4 + slice*512 + qi*64 + 4*j) =
                make_ulonglong2(aclo[qi], achi[qi]);
    }
    __syncthreads();

    // reduce 16 k-slices -> global out
    {
        int qi = tid >> 5, e = (tid & 31) * 2;
        float sx = 0.f, sy = 0.f;
#pragma unroll
        for (int s = 0; s < 16; s++) {
            float2 p = *(const float2*)(sm + SM_P4 + s*512 + qi*64 + e);
            sx += p.x; sy += p.y;
        }
        *(float2*)(out + (q0 + qi)*DOUT + e) = make_float2(sx, sy);
    }
}

extern "C" void kernel_launch(void* const* d_in, const int* in_sizes, int n_in,
                              void* d_out, int out_size)
{
    const float* qp    = (const float*)d_in[0];
    const float* sp    = (const float*)d_in[1];
    const int*   neigh = (const int*)  d_in[2];
    const float* x     = (const float*)d_in[3];
    const float* kpts  = (const float*)d_in[4];
    const float* ow    = (const float*)d_in[5];
    const float* obias = (const float*)d_in[6];
    const float* w     = (const float*)d_in[7];
    float* out = (float*)d_out;

    prep_owpad<<<(KD*ODP + 255)/256, 256>>>(ow);

    cudaFuncSetAttribute(kpconv_deform_fused,
                         cudaFuncAttributeMaxDynamicSharedMemorySize, SMEM_BYTES);

    kpconv_deform_fused<<<NQ/QPB, NTHREADS, SMEM_BYTES>>>(
        qp, sp, neigh, x, kpts, obias, w, out);
}